// round 12
// baseline (speedup 1.0000x reference)
#include <cuda_runtime.h>
#include <cuda_bf16.h>

// Problem constants (fixed by the reference)
#define N_USERS 100000
#define N_ITEMS 100000
#define NTOT    (N_USERS + N_ITEMS)   // 200000
#define EMBD    64
#define NNZ_E   1000000
#define NELEMS  (NTOT * EMBD)         // 12,800,000 floats

#define SCAN_BLK   1024
#define SCAN_NBLK  ((NTOT + SCAN_BLK - 1) / SCAN_BLK)   // 196

// Allocation-free scratch (__device__ globals)
__device__ int   g_counts[NTOT];       // per-row degree
__device__ int   g_rowstart[NTOT];     // CSR row offsets (exclusive scan)
__device__ int   g_cursor[NTOT];       // scatter cursors
__device__ int   g_blocksums[SCAN_NBLK];
__device__ int2  g_sedge[NNZ_E];       // row-sorted edges: {col, f32 bits of val}
__device__ float g_y1[NELEMS];
__device__ float g_y2[NELEMS];

// ======================= CSR build (once per call) =========================

__global__ void k_clear(int* __restrict__ counts)
{
    int i = blockIdx.x * blockDim.x + threadIdx.x;
    if (i < NTOT) counts[i] = 0;
}

__global__ void k_hist(const int* __restrict__ rows, int* __restrict__ counts)
{
    int e = blockIdx.x * blockDim.x + threadIdx.x;
    if (e < NNZ_E) atomicAdd(&counts[__ldg(rows + e)], 1);
}

// Per-block exclusive scan + block totals (Hillis-Steele in smem)
__global__ void k_scan1(const int* __restrict__ counts,
                        int* __restrict__ block_sums,
                        int* __restrict__ excl)
{
    __shared__ int sh[SCAN_BLK];
    int i = blockIdx.x * SCAN_BLK + threadIdx.x;
    int v = (i < NTOT) ? counts[i] : 0;
    sh[threadIdx.x] = v;
    __syncthreads();
    #pragma unroll
    for (int off = 1; off < SCAN_BLK; off <<= 1) {
        int t = (threadIdx.x >= off) ? sh[threadIdx.x - off] : 0;
        __syncthreads();
        sh[threadIdx.x] += t;
        __syncthreads();
    }
    if (i < NTOT) excl[i] = sh[threadIdx.x] - v;   // exclusive within block
    if (threadIdx.x == SCAN_BLK - 1) block_sums[blockIdx.x] = sh[threadIdx.x];
}

// Single-block exclusive scan of the block totals (n <= 256)
__global__ void k_scan2(int* __restrict__ block_sums, int n)
{
    __shared__ int sh[256];
    int v = (threadIdx.x < n) ? block_sums[threadIdx.x] : 0;
    sh[threadIdx.x] = v;
    __syncthreads();
    #pragma unroll
    for (int off = 1; off < 256; off <<= 1) {
        int t = (threadIdx.x >= off) ? sh[threadIdx.x - off] : 0;
        __syncthreads();
        sh[threadIdx.x] += t;
        __syncthreads();
    }
    if (threadIdx.x < n) block_sums[threadIdx.x] = sh[threadIdx.x] - v;
}

// Add block offsets -> final row_start; seed cursors
__global__ void k_scan3(int* __restrict__ rowstart,
                        const int* __restrict__ block_sums,
                        int* __restrict__ cursor)
{
    int i = blockIdx.x * blockDim.x + threadIdx.x;
    if (i >= NTOT) return;
    int s = rowstart[i] + block_sums[i / SCAN_BLK];
    rowstart[i] = s;
    cursor[i]   = s;
}

// Bucket edges by destination row
__global__ void k_scatter(const int*   __restrict__ rows,
                          const int*   __restrict__ cols,
                          const float* __restrict__ vals,
                          int*         __restrict__ cursor,
                          int2*        __restrict__ sedge)
{
    int e = blockIdx.x * blockDim.x + threadIdx.x;
    if (e >= NNZ_E) return;
    int r   = __ldg(rows + e);
    int pos = atomicAdd(&cursor[r], 1);
    int2 pk;
    pk.x = __ldg(cols + e);
    pk.y = __float_as_int(__ldg(vals + e));
    sedge[pos] = pk;
}

// ======================= CSR SpMM (pull, no atomics) =======================
// 16 threads per output row; thread p owns float4 slot p. Loop over the row's
// edges (2-way unrolled -> 2 independent gathers in flight), ONE plain store.

__device__ __forceinline__ void fma4(float4& acc, float v, float4 x)
{
    acc.x += v * x.x; acc.y += v * x.y; acc.z += v * x.z; acc.w += v * x.w;
}

__global__ void k_csr_spmm(const int*  __restrict__ rowstart,
                           const int*  __restrict__ counts,
                           const int2* __restrict__ sedge,
                           const float* __restrict__ x,
                           float*       __restrict__ y)
{
    long long tid = (long long)blockIdx.x * blockDim.x + threadIdx.x;
    int r = (int)(tid >> 4);
    int p = (int)(tid & 15);
    if (r >= NTOT) return;

    int s = __ldg(rowstart + r);
    int n = __ldg(counts + r);

    float4 acc = make_float4(0.f, 0.f, 0.f, 0.f);
    int j = 0;
    for (; j + 1 < n; j += 2) {
        int2 e0 = __ldg(sedge + s + j);
        int2 e1 = __ldg(sedge + s + j + 1);
        float4 xa = __ldg((const float4*)(x + (long long)e0.x * EMBD) + p);
        float4 xb = __ldg((const float4*)(x + (long long)e1.x * EMBD) + p);
        fma4(acc, __int_as_float(e0.y), xa);
        fma4(acc, __int_as_float(e1.y), xb);
    }
    if (j < n) {
        int2 e0 = __ldg(sedge + s + j);
        float4 xa = __ldg((const float4*)(x + (long long)e0.x * EMBD) + p);
        fma4(acc, __int_as_float(e0.y), xa);
    }
    ((float4*)(y + (long long)r * EMBD))[p] = acc;
}

// Layer 0: gather from the virtual concat(user_w, item_w)
__global__ void k_csr_spmm_first(const int*  __restrict__ rowstart,
                                 const int*  __restrict__ counts,
                                 const int2* __restrict__ sedge,
                                 const float* __restrict__ user_w,
                                 const float* __restrict__ item_w,
                                 float*       __restrict__ y)
{
    long long tid = (long long)blockIdx.x * blockDim.x + threadIdx.x;
    int r = (int)(tid >> 4);
    int p = (int)(tid & 15);
    if (r >= NTOT) return;

    int s = __ldg(rowstart + r);
    int n = __ldg(counts + r);

    float4 acc = make_float4(0.f, 0.f, 0.f, 0.f);
    int j = 0;
    for (; j + 1 < n; j += 2) {
        int2 e0 = __ldg(sedge + s + j);
        int2 e1 = __ldg(sedge + s + j + 1);
        const float* xr0 = (e0.x < N_USERS) ? (user_w + (long long)e0.x * EMBD)
                                            : (item_w + (long long)(e0.x - N_USERS) * EMBD);
        const float* xr1 = (e1.x < N_USERS) ? (user_w + (long long)e1.x * EMBD)
                                            : (item_w + (long long)(e1.x - N_USERS) * EMBD);
        float4 xa = __ldg((const float4*)xr0 + p);
        float4 xb = __ldg((const float4*)xr1 + p);
        fma4(acc, __int_as_float(e0.y), xa);
        fma4(acc, __int_as_float(e1.y), xb);
    }
    if (j < n) {
        int2 e0 = __ldg(sedge + s + j);
        const float* xr0 = (e0.x < N_USERS) ? (user_w + (long long)e0.x * EMBD)
                                            : (item_w + (long long)(e0.x - N_USERS) * EMBD);
        float4 xa = __ldg((const float4*)xr0 + p);
        fma4(acc, __int_as_float(e0.y), xa);
    }
    ((float4*)(y + (long long)r * EMBD))[p] = acc;
}

// Layer 2 fused with the mean: out[r] = 0.25*(x0[r] + y1[r] + y2[r] + A@y2[r])
__global__ void k_csr_spmm_final(const int*  __restrict__ rowstart,
                                 const int*  __restrict__ counts,
                                 const int2* __restrict__ sedge,
                                 const float* __restrict__ y2,     // gather src
                                 const float* __restrict__ user_w,
                                 const float* __restrict__ item_w,
                                 const float* __restrict__ y1,
                                 float*       __restrict__ out)
{
    long long tid = (long long)blockIdx.x * blockDim.x + threadIdx.x;
    int r = (int)(tid >> 4);
    int p = (int)(tid & 15);
    if (r >= NTOT) return;

    int s = __ldg(rowstart + r);
    int n = __ldg(counts + r);

    float4 acc = make_float4(0.f, 0.f, 0.f, 0.f);
    int j = 0;
    for (; j + 1 < n; j += 2) {
        int2 e0 = __ldg(sedge + s + j);
        int2 e1 = __ldg(sedge + s + j + 1);
        float4 xa = __ldg((const float4*)(y2 + (long long)e0.x * EMBD) + p);
        float4 xb = __ldg((const float4*)(y2 + (long long)e1.x * EMBD) + p);
        fma4(acc, __int_as_float(e0.y), xa);
        fma4(acc, __int_as_float(e1.y), xb);
    }
    if (j < n) {
        int2 e0 = __ldg(sedge + s + j);
        float4 xa = __ldg((const float4*)(y2 + (long long)e0.x * EMBD) + p);
        fma4(acc, __int_as_float(e0.y), xa);
    }

    // Residual terms for this row (coalesced reads)
    const float* x0r = (r < N_USERS) ? (user_w + (long long)r * EMBD)
                                     : (item_w + (long long)(r - N_USERS) * EMBD);
    float4 x  = __ldg((const float4*)x0r + p);
    float4 a  = __ldg((const float4*)(y1 + (long long)r * EMBD) + p);
    float4 b  = __ldg((const float4*)(y2 + (long long)r * EMBD) + p);

    float4 o;
    o.x = (x.x + a.x + b.x + acc.x) * 0.25f;
    o.y = (x.y + a.y + b.y + acc.y) * 0.25f;
    o.z = (x.z + a.z + b.z + acc.z) * 0.25f;
    o.w = (x.w + a.w + b.w + acc.w) * 0.25f;
    ((float4*)(out + (long long)r * EMBD))[p] = o;
}

extern "C" void kernel_launch(void* const* d_in, const int* in_sizes, int n_in,
                              void* d_out, int out_size)
{
    const float* user_w = (const float*)d_in[0];
    const float* item_w = (const float*)d_in[1];
    const float* vals   = (const float*)d_in[2];
    const int*   rows   = (const int*)d_in[3];
    const int*   cols   = (const int*)d_in[4];
    float*       out    = (float*)d_out;

    int *counts, *rowstart, *cursor, *blocksums;
    int2 *sedge;
    float *y1, *y2;
    cudaGetSymbolAddress((void**)&counts,    g_counts);
    cudaGetSymbolAddress((void**)&rowstart,  g_rowstart);
    cudaGetSymbolAddress((void**)&cursor,    g_cursor);
    cudaGetSymbolAddress((void**)&blocksums, g_blocksums);
    cudaGetSymbolAddress((void**)&sedge,     g_sedge);
    cudaGetSymbolAddress((void**)&y1,        g_y1);
    cudaGetSymbolAddress((void**)&y2,        g_y2);

    const int TB = 256;
    const int gridRow  = (NTOT + TB - 1) / TB;          // 782
    const int gridEdge = (NNZ_E + TB - 1) / TB;         // 3907
    const int gridSpmm = (NTOT * 16 + TB - 1) / TB;     // 12500

    // ---- CSR build (amortized over 3 layers) ----
    k_clear  <<<gridRow,  TB>>>(counts);
    k_hist   <<<gridEdge, TB>>>(rows, counts);
    k_scan1  <<<SCAN_NBLK, SCAN_BLK>>>(counts, blocksums, rowstart);
    k_scan2  <<<1, 256>>>(blocksums, SCAN_NBLK);
    k_scan3  <<<gridRow,  TB>>>(rowstart, blocksums, cursor);
    k_scatter<<<gridEdge, TB>>>(rows, cols, vals, cursor, sedge);

    // ---- Propagation (pull-mode, no atomics, no zeroing) ----
    // y1 = A @ x0   (x0 = concat(user_w,item_w), read in place)
    k_csr_spmm_first<<<gridSpmm, TB>>>(rowstart, counts, sedge,
                                       user_w, item_w, y1);
    // y2 = A @ y1
    k_csr_spmm<<<gridSpmm, TB>>>(rowstart, counts, sedge, y1, y2);
    // out = 0.25*(x0 + y1 + y2 + A @ y2)
    k_csr_spmm_final<<<gridSpmm, TB>>>(rowstart, counts, sedge, y2,
                                       user_w, item_w, y1, out);
}